// round 1
// baseline (speedup 1.0000x reference)
#include <cuda_runtime.h>
#include <math_constants.h>

// ---------------------------------------------------------------------------
// NeuralSpectralBlock2D  (B=16, C=64, H=W=240, P=3, HEAD=8, dh=8, T=4, M=12)
// Fully fused per-patch kernel. One warp = one patch; CTA = 16 patches.
// k-path folded into scores1 via A = latent^T * enc_w_k (patch-invariant).
// ---------------------------------------------------------------------------

#define Bn    16
#define Cn    64
#define Hn    240
#define Wn    240
#define Pn    3
#define Ln    9
#define HEADn 8
#define DHn   8
#define Tn    4
#define Mn    12
#define NP    16          // patches per CTA
#define NT    512         // threads per CTA (16 warps)

#define HPn   (Hn / Pn)   // 80
#define WPn   (Wn / Pn)   // 80
#define WBLK  (WPn / NP)  // 5 patch-blocks per row
#define GRID  (Bn * HPn * WBLK)  // 6400

// Folded constants, packed into one buffer (float offsets)
#define OFF_A   0                 // [c][ht]  64*32
#define OFF_C1  (OFF_A  + 2048)   // [ht]     32
#define OFF_WV  (OFF_C1 + 32)     // [c][hd]  64*64
#define OFF_BV  (OFF_WV + 4096)   // [hd]     64
#define OFF_WD  (OFF_BV + 64)     // [c][o]   64*64
#define OFF_BD  (OFF_WD + 4096)   // [o]      64
#define OFF_WT  (OFF_BD + 64)     // [m'][c]  24*64
#define OFF_Q   (OFF_WT + 1536)   // [hd][t]  64*4
#define CONST_F (OFF_Q  + 256)    // 12192 floats

#define XPS     577               // padded per-patch xp stride (bank-conflict-free)
#define SMEM_F  (CONST_F + NP*XPS + NP*288 + NP*576 + NP*256)
#define SMEM_B  (SMEM_F * 4)

__device__ float g_const[CONST_F];

__global__ void setup_kernel(const float* __restrict__ latent,
                             const float* __restrict__ weights,
                             const float* __restrict__ enc_w,
                             const float* __restrict__ enc_b,
                             const float* __restrict__ dec_w,
                             const float* __restrict__ dec_b) {
    int tid = threadIdx.x;
    // A[c][ht] = sum_d latent[h,t,d] * enc_w[h*16+2d, c]   (k-path fold)
    for (int i = tid; i < 64 * 32; i += blockDim.x) {
        int c = i >> 5, ht = i & 31;
        int h = ht >> 2, t = ht & 3;
        float s = 0.f;
        for (int d = 0; d < 8; d++)
            s += latent[h * 32 + t * 8 + d] * enc_w[(h * 16 + 2 * d) * 64 + c];
        g_const[OFF_A + c * 32 + ht] = s;
    }
    // c1[ht] = sum_d latent[h,t,d] * enc_b[h*16+2d]
    for (int i = tid; i < 32; i += blockDim.x) {
        int h = i >> 2, t = i & 3;
        float s = 0.f;
        for (int d = 0; d < 8; d++)
            s += latent[h * 32 + t * 8 + d] * enc_b[h * 16 + 2 * d];
        g_const[OFF_C1 + i] = s;
    }
    // Wv[c][hd] = enc_w[h*16+2d+1, c] ;  Wd[c][o] = dec_w[o, c]
    for (int i = tid; i < 64 * 64; i += blockDim.x) {
        int c = i >> 6, hd = i & 63;
        int h = hd >> 3, d = hd & 7;
        g_const[OFF_WV + i] = enc_w[(h * 16 + 2 * d + 1) * 64 + c];
        g_const[OFF_WD + i] = dec_w[hd * 64 + c];
    }
    for (int i = tid; i < 64; i += blockDim.x) {
        int h = i >> 3, d = i & 7;
        g_const[OFF_BV + i] = enc_b[h * 16 + 2 * d + 1];
        g_const[OFF_BD + i] = dec_b[i];
    }
    // wt[m'][c] = weights[c][m']   (m' in 0..23 : 0..11 sin, 12..23 cos)
    for (int i = tid; i < 24 * 64; i += blockDim.x) {
        int m = i >> 6, c = i & 63;
        g_const[OFF_WT + i] = weights[c * 24 + m];
    }
    // q[hd][t] = latent[h,t,d]
    for (int i = tid; i < 256; i += blockDim.x) {
        int hd = i >> 2, t = i & 3;
        int h = hd >> 3, d = hd & 7;
        g_const[OFF_Q + i] = latent[h * 32 + t * 8 + d];
    }
}

__global__ void __launch_bounds__(NT, 1)
nsb_kernel(const float* __restrict__ x, float* __restrict__ out) {
    extern __shared__ float sm[];
    float* sA  = sm + OFF_A;
    float* sc1 = sm + OFF_C1;
    float* sWv = sm + OFF_WV;
    float* sbv = sm + OFF_BV;
    float* sWd = sm + OFF_WD;
    float* sbd = sm + OFF_BD;
    float* swt = sm + OFF_WT;
    float* sq  = sm + OFF_Q;
    float* sxp = sm + CONST_F;          // [NP][XPS]   patch pixels  [c*9+pos]
    float* sat = sxp + NP * XPS;        // [NP][288]   attn1         [ht*9+pos]
    float* sxq = sat + NP * 288;        // [NP][576]   xq -> xo      [c*9+pos]
    float* slt = sxq + NP * 576;        // [NP][256]   ltp           [c*4+t]

    const int tid = threadIdx.x;

    // ---- load folded constants (coalesced, L2-resident) ----
    for (int i = tid; i < CONST_F; i += NT) sm[i] = g_const[i];

    // ---- decode CTA -> (b, hp, wblk) ----
    const int cta  = blockIdx.x;
    const int wblk = cta % WBLK;
    const int hp   = (cta / WBLK) % HPn;
    const int b    = cta / (WBLK * HPn);

    // ---- cooperative patchify load: 64 ch x 3 rows x 48 cols ----
    for (int i = tid; i < 64 * 3 * 48; i += NT) {
        int col = i % 48;
        int seg = i / 48;
        int p0  = seg % 3;
        int c   = seg / 3;
        int wl  = col / 3, p1 = col % 3;
        float v = x[((b * 64 + c) * Hn + hp * 3 + p0) * Wn + wblk * 48 + col];
        sxp[wl * XPS + c * 9 + p0 * 3 + p1] = v;
    }
    __syncthreads();

    // ---- per-warp patch compute ----
    const int warp = tid >> 5;
    const int lane = tid & 31;
    float* xp = sxp + warp * XPS;
    float* at = sat + warp * 288;
    float* xq = sxq + warp * 576;
    float* lp = slt + warp * 256;

    // accumulators: scores1 (lane = ht), v rows (hd = lane, lane+32),
    // dec rows (o = lane, lane+32)
    float s1[9], v0[9], v1[9], u0[9], u1[9];
    {
        float c1v = sc1[lane];
        float b0  = sbv[lane],  b1 = sbv[lane + 32];
        float e0  = sbd[lane],  e1 = sbd[lane + 32];
#pragma unroll
        for (int p = 0; p < 9; p++) {
            s1[p] = c1v; v0[p] = b0; v1[p] = b1; u0[p] = e0; u1[p] = e1;
        }
    }
    // fused c-loop: 14 LDS + 45 FFMA per c
    for (int c = 0; c < 64; c++) {
        float a  = sA [c * 32 + lane];
        float w0 = sWv[c * 64 + lane], w1 = sWv[c * 64 + lane + 32];
        float d0 = sWd[c * 64 + lane], d1 = sWd[c * 64 + lane + 32];
        const float* xr = xp + c * 9;
#pragma unroll
        for (int p = 0; p < 9; p++) {
            float xv = xr[p];
            s1[p] = fmaf(a,  xv, s1[p]);
            v0[p] = fmaf(w0, xv, v0[p]);
            v1[p] = fmaf(w1, xv, v1[p]);
            u0[p] = fmaf(d0, xv, u0[p]);
            u1[p] = fmaf(d1, xv, u1[p]);
        }
    }

    // softmax over pos (lane = ht) -> attn1 to shared
    {
        float mx = s1[0];
#pragma unroll
        for (int p = 1; p < 9; p++) mx = fmaxf(mx, s1[p]);
        float sum = 0.f;
#pragma unroll
        for (int p = 0; p < 9; p++) { s1[p] = __expf(s1[p] - mx); sum += s1[p]; }
        float inv = 1.0f / sum;
#pragma unroll
        for (int p = 0; p < 9; p++) at[lane * 9 + p] = s1[p] * inv;
    }
    // stash xq rows (bias already folded)
#pragma unroll
    for (int p = 0; p < 9; p++) {
        xq[lane * 9 + p]        = u0[p];
        xq[(lane + 32) * 9 + p] = u1[p];
    }
    __syncwarp();

    // lt[h,t,d] = attn1 @ v + q   (lane owns channels c0=lane, c1=lane+32)
    const int h0 = lane >> 3, h1 = 4 + (lane >> 3);
    float lt0[4], lt1[4];
#pragma unroll
    for (int t = 0; t < 4; t++) {
        float a0 = sq[lane * 4 + t], a1 = sq[(lane + 32) * 4 + t];
        const float* r0 = at + (h0 * 4 + t) * 9;
        const float* r1 = at + (h1 * 4 + t) * 9;
#pragma unroll
        for (int p = 0; p < 9; p++) {
            a0 = fmaf(r0[p], v0[p], a0);
            a1 = fmaf(r1[p], v1[p], a1);
        }
        lt0[t] = a0; lt1[t] = a1;
    }

    // spectral basis mixing: ltp = lt + sum_m sin(ang)*w[m] + cos(ang)*w[M+m]
#pragma unroll
    for (int t = 0; t < 4; t++) {
        float base0 = lt0[t] * (float)(CUDART_PI / 12.0);
        float base1 = lt1[t] * (float)(CUDART_PI / 12.0);
        float acc0 = 0.f, acc1 = 0.f;
#pragma unroll
        for (int m = 0; m < 12; m++) {
            float sn, cs;
            __sincosf(base0 * (float)m, &sn, &cs);
            acc0 = fmaf(sn, swt[m * 64 + lane],
                   fmaf(cs, swt[(12 + m) * 64 + lane], acc0));
            __sincosf(base1 * (float)m, &sn, &cs);
            acc1 = fmaf(sn, swt[m * 64 + lane + 32],
                   fmaf(cs, swt[(12 + m) * 64 + lane + 32], acc1));
        }
        lp[lane * 4 + t]        = lt0[t] + acc0;
        lp[(lane + 32) * 4 + t] = lt1[t] + acc1;
    }
    __syncwarp();

    // decoder attention: 72 (h,pos) items; attn2 over t; xo in-place into xq
#pragma unroll
    for (int k = 0; k < 3; k++) {
        int item = lane + 32 * k;
        if (item < 72) {
            int h = item / 9, pos = item - h * 9;
            float ltc[32];
            float sc[4] = {0.f, 0.f, 0.f, 0.f};
#pragma unroll
            for (int d = 0; d < 8; d++) {
                float xv = xq[(h * 8 + d) * 9 + pos];
#pragma unroll
                for (int t = 0; t < 4; t++) {
                    float l = lp[(h * 8 + d) * 4 + t];
                    ltc[d * 4 + t] = l;
                    sc[t] = fmaf(xv, l, sc[t]);
                }
            }
            float m2 = fmaxf(fmaxf(sc[0], sc[1]), fmaxf(sc[2], sc[3]));
            float es = 0.f;
#pragma unroll
            for (int t = 0; t < 4; t++) { sc[t] = __expf(sc[t] - m2); es += sc[t]; }
            float inv = 1.0f / es;
#pragma unroll
            for (int t = 0; t < 4; t++) sc[t] *= inv;
#pragma unroll
            for (int d = 0; d < 8; d++) {
                float o = 0.f;
#pragma unroll
                for (int t = 0; t < 4; t++) o = fmaf(sc[t], ltc[d * 4 + t], o);
                xq[(h * 8 + d) * 9 + pos] = o;   // in-place: lane owns these slots
            }
        }
    }
    __syncthreads();

    // ---- cooperative un-patchify store with residual ----
    for (int i = tid; i < 64 * 3 * 48; i += NT) {
        int col = i % 48;
        int seg = i / 48;
        int p0  = seg % 3;
        int c   = seg / 3;
        int wl  = col / 3, p1 = col % 3;
        int li  = c * 9 + p0 * 3 + p1;
        out[((b * 64 + c) * Hn + hp * 3 + p0) * Wn + wblk * 48 + col] =
            sxq[wl * 576 + li] + sxp[wl * XPS + li];
    }
}

extern "C" void kernel_launch(void* const* d_in, const int* in_sizes, int n_in,
                              void* d_out, int out_size) {
    const float* x       = (const float*)d_in[0];
    const float* latent  = (const float*)d_in[1];
    const float* weights = (const float*)d_in[2];
    const float* enc_w   = (const float*)d_in[3];
    const float* enc_b   = (const float*)d_in[4];
    const float* dec_w   = (const float*)d_in[5];
    const float* dec_b   = (const float*)d_in[6];
    float* out = (float*)d_out;

    cudaFuncSetAttribute(nsb_kernel,
                         cudaFuncAttributeMaxDynamicSharedMemorySize, SMEM_B);

    setup_kernel<<<1, 256>>>(latent, weights, enc_w, enc_b, dec_w, dec_b);
    nsb_kernel<<<GRID, NT, SMEM_B>>>(x, out);
}

// round 2
// speedup vs baseline: 1.3171x; 1.3171x over previous
#include <cuda_runtime.h>
#include <math_constants.h>

// ---------------------------------------------------------------------------
// NeuralSpectralBlock2D  (B=16, C=64, H=W=240, P=3, HEAD=8, dh=8, T=4, M=12)
// One warp = one patch; CTA = 256 threads = 8 patches. Packed f32x2 FMA in
// the channel loop; weights streamed via LDG (L1); k-path folded offline.
// ---------------------------------------------------------------------------

#define Bn    16
#define Cn    64
#define Hn    240
#define Wn    240
#define NP    8           // patches per CTA
#define NT    256         // threads per CTA (8 warps)

#define HPn   80
#define WPn   80
#define WBLK  (WPn / NP)          // 10
#define GRID  (Bn * HPn * WBLK)   // 12800

// ---- global folded-constant buffer (float offsets) ----
#define OFF_A   0        // A[c*32+lane]                        2048
#define OFF_WV  2048     // WV[c*32+lane] float2 {w0,w1}        4096
#define OFF_WD  6144     // WD[c*32+lane] float2 {d0,d1}        4096
#define OFF_SM  10240    // small block -> copied to smem       1952
#define CONST_F 12192

// small-const block offsets (within smem copy)
#define S_C1  0          // c1[ht]        32
#define S_BV  32         // bv[hd]        64
#define S_BD  96         // bd[o]         64
#define S_WT  160        // wt[m'][c]     1536
#define S_Q   1696       // q[hd][t]      256
#define S_SZ  1952

// ---- shared layout (floats) ----
#define XPS   770        // per-patch xp stride ([c*12+pos], pos 0..8)
#define ATS   288        // attn1 [ht*9+pos]
#define XQS   640        // xq/xo [ch*10+pos]
#define LTS   320        // lt'   [ch*5+t]
#define SM_XP (S_SZ)
#define SM_AT (SM_XP + NP*XPS)
#define SM_XQ (SM_AT + NP*ATS)
#define SM_LT (SM_XQ + NP*XQS)
#define SMEM_F (SM_LT + NP*LTS)
#define SMEM_B (SMEM_F * 4)       // 72384 bytes

__device__ __align__(16) float g_const[CONST_F];

// ---------------- f32x2 helpers ----------------
__device__ __forceinline__ unsigned long long ffma2(unsigned long long a,
                                                    unsigned long long b,
                                                    unsigned long long c) {
    unsigned long long d;
    asm("fma.rn.f32x2 %0, %1, %2, %3;" : "=l"(d) : "l"(a), "l"(b), "l"(c));
    return d;
}
__device__ __forceinline__ unsigned long long splat2(float x) {
    unsigned long long r;
    unsigned u = __float_as_uint(x);
    asm("mov.b64 %0, {%1, %1};" : "=l"(r) : "r"(u));
    return r;
}
__device__ __forceinline__ float2 unpack2(unsigned long long v) {
    float lo, hi;
    asm("mov.b64 {%0, %1}, %2;" : "=f"(lo), "=f"(hi) : "l"(v));
    return make_float2(lo, hi);
}

// ---------------- setup: fold constants ----------------
__global__ void setup_kernel(const float* __restrict__ latent,
                             const float* __restrict__ weights,
                             const float* __restrict__ enc_w,
                             const float* __restrict__ enc_b,
                             const float* __restrict__ dec_w,
                             const float* __restrict__ dec_b) {
    int tid = threadIdx.x + blockIdx.x * blockDim.x;
    // A[c][ht] = sum_d latent[h,t,d] * enc_w[(h*16+2d)*64 + c]
    for (int i = tid; i < 2048; i += 256) {
        int c = i >> 5, ht = i & 31;
        int h = ht >> 2, t = ht & 3;
        float s = 0.f;
        for (int d = 0; d < 8; d++)
            s += latent[h * 32 + t * 8 + d] * enc_w[(h * 16 + 2 * d) * 64 + c];
        g_const[OFF_A + i] = s;
    }
    // WV/WD float2 per (c, lane)
    for (int i = tid; i < 2048; i += 256) {
        int c = i >> 5, lane = i & 31;
        int h0 = lane >> 3, d0 = lane & 7;
        int l1 = lane + 32;
        int h1 = l1 >> 3, d1 = l1 & 7;
        g_const[OFF_WV + 2 * i + 0] = enc_w[(h0 * 16 + 2 * d0 + 1) * 64 + c];
        g_const[OFF_WV + 2 * i + 1] = enc_w[(h1 * 16 + 2 * d1 + 1) * 64 + c];
        g_const[OFF_WD + 2 * i + 0] = dec_w[lane * 64 + c];
        g_const[OFF_WD + 2 * i + 1] = dec_w[l1 * 64 + c];
    }
    // small block
    for (int i = tid; i < 32; i += 256) {           // c1
        int h = i >> 2, t = i & 3;
        float s = 0.f;
        for (int d = 0; d < 8; d++)
            s += latent[h * 32 + t * 8 + d] * enc_b[h * 16 + 2 * d];
        g_const[OFF_SM + S_C1 + i] = s;
    }
    for (int i = tid; i < 64; i += 256) {           // bv, bd
        int h = i >> 3, d = i & 7;
        g_const[OFF_SM + S_BV + i] = enc_b[h * 16 + 2 * d + 1];
        g_const[OFF_SM + S_BD + i] = dec_b[i];
    }
    for (int i = tid; i < 1536; i += 256) {         // wt[m'][c]
        int m = i >> 6, c = i & 63;
        g_const[OFF_SM + S_WT + i] = weights[c * 24 + m];
    }
    for (int i = tid; i < 256; i += 256) {          // q[hd][t]
        int hd = i >> 2, t = i & 3;
        int h = hd >> 3, d = hd & 7;
        g_const[OFF_SM + S_Q + i] = latent[h * 32 + t * 8 + d];
    }
}

// ---------------- main fused kernel ----------------
__global__ void __launch_bounds__(NT, 3)
nsb_kernel(const float* __restrict__ x, float* __restrict__ out) {
    extern __shared__ float sm[];
    float* ss  = sm;             // small consts
    float* sxp = sm + SM_XP;
    float* sat = sm + SM_AT;
    float* sxq = sm + SM_XQ;
    float* slt = sm + SM_LT;

    const int tid = threadIdx.x;

    // small consts -> smem
    for (int i = tid; i < S_SZ; i += NT) ss[i] = g_const[OFF_SM + i];

    // CTA -> (b, hp, wblk)
    const int cta  = blockIdx.x;
    const int wblk = cta % WBLK;
    const int hp   = (cta / WBLK) % HPn;
    const int b    = cta / (WBLK * HPn);

    // cooperative patchify load: 64 ch x 3 rows x 24 cols
    for (int i = tid; i < 64 * 3 * 24; i += NT) {
        int col = i % 24;
        int seg = i / 24;
        int p0  = seg % 3;
        int c   = seg / 3;
        int wl  = col / 3, p1 = col % 3;
        float v = x[((b * 64 + c) * Hn + hp * 3 + p0) * Wn + wblk * 24 + col];
        sxp[wl * XPS + c * 12 + p0 * 3 + p1] = v;
    }
    __syncthreads();

    const int warp = tid >> 5;
    const int lane = tid & 31;
    float* xp = sxp + warp * XPS;
    float* at = sat + warp * ATS;
    float* xq = sxq + warp * XQS;
    float* lp = slt + warp * LTS;

    const float* gA  = g_const + OFF_A;
    const float2* gWV = (const float2*)(g_const + OFF_WV);
    const float2* gWD = (const float2*)(g_const + OFF_WD);

    // ================= pass A: scores1 + v =================
    unsigned long long s1p[4], v0p[4], v1p[4];
    float s1l, v0l, v1l;
    {
        float c1v = ss[S_C1 + lane];
        float b0 = ss[S_BV + lane], b1 = ss[S_BV + lane + 32];
        unsigned long long c1s = splat2(c1v), b0s = splat2(b0), b1s = splat2(b1);
#pragma unroll
        for (int j = 0; j < 4; j++) { s1p[j] = c1s; v0p[j] = b0s; v1p[j] = b1s; }
        s1l = c1v; v0l = b0; v1l = b1;
    }
#pragma unroll 4
    for (int c = 0; c < 64; c++) {
        float a   = __ldg(gA + c * 32 + lane);
        float2 wv = __ldg(gWV + c * 32 + lane);
        unsigned long long ap  = splat2(a);
        unsigned long long w0p = splat2(wv.x);
        unsigned long long w1p = splat2(wv.y);
        const float* xr = xp + c * 12;
        unsigned long long xx[4];
#pragma unroll
        for (int j = 0; j < 4; j++)
            xx[j] = *(const unsigned long long*)(xr + 2 * j);
        float x8 = xr[8];
#pragma unroll
        for (int j = 0; j < 4; j++) {
            s1p[j] = ffma2(ap,  xx[j], s1p[j]);
            v0p[j] = ffma2(w0p, xx[j], v0p[j]);
            v1p[j] = ffma2(w1p, xx[j], v1p[j]);
        }
        s1l = fmaf(a,    x8, s1l);
        v0l = fmaf(wv.x, x8, v0l);
        v1l = fmaf(wv.y, x8, v1l);
    }
    // unpack
    float s1[9], v0[9], v1[9];
#pragma unroll
    for (int j = 0; j < 4; j++) {
        float2 f;
        f = unpack2(s1p[j]); s1[2 * j] = f.x; s1[2 * j + 1] = f.y;
        f = unpack2(v0p[j]); v0[2 * j] = f.x; v0[2 * j + 1] = f.y;
        f = unpack2(v1p[j]); v1[2 * j] = f.x; v1[2 * j + 1] = f.y;
    }
    s1[8] = s1l; v0[8] = v0l; v1[8] = v1l;

    // softmax over pos (lane = ht) -> attn1 to shared
    {
        float mx = s1[0];
#pragma unroll
        for (int p = 1; p < 9; p++) mx = fmaxf(mx, s1[p]);
        float sum = 0.f;
#pragma unroll
        for (int p = 0; p < 9; p++) { s1[p] = __expf(s1[p] - mx); sum += s1[p]; }
        float inv = 1.0f / sum;
#pragma unroll
        for (int p = 0; p < 9; p++) at[lane * 9 + p] = s1[p] * inv;
    }
    __syncwarp();

    // lt[h,t,d] = attn1 @ v + q   (lane owns channels lane, lane+32)
    const int h0 = lane >> 3;
    float lt0[4], lt1[4];
#pragma unroll
    for (int t = 0; t < 4; t++) {
        float a0 = ss[S_Q + lane * 4 + t];
        float a1 = ss[S_Q + (lane + 32) * 4 + t];
        const float* r0 = at + (h0 * 4 + t) * 9;
        const float* r1 = at + ((h0 + 4) * 4 + t) * 9;
#pragma unroll
        for (int p = 0; p < 9; p++) {
            a0 = fmaf(r0[p], v0[p], a0);
            a1 = fmaf(r1[p], v1[p], a1);
        }
        lt0[t] = a0; lt1[t] = a1;
    }

    // spectral basis mixing -> lp[ch*5+t]
#pragma unroll
    for (int t = 0; t < 4; t++) {
        float base0 = lt0[t] * (float)(CUDART_PI / 12.0);
        float base1 = lt1[t] * (float)(CUDART_PI / 12.0);
        float acc0 = ss[S_WT + 12 * 64 + lane];        // m=0: sin=0, cos=1
        float acc1 = ss[S_WT + 12 * 64 + lane + 32];
#pragma unroll
        for (int m = 1; m < 12; m++) {
            float sn, cs;
            __sincosf(base0 * (float)m, &sn, &cs);
            acc0 = fmaf(sn, ss[S_WT + m * 64 + lane],
                   fmaf(cs, ss[S_WT + (12 + m) * 64 + lane], acc0));
            __sincosf(base1 * (float)m, &sn, &cs);
            acc1 = fmaf(sn, ss[S_WT + m * 64 + lane + 32],
                   fmaf(cs, ss[S_WT + (12 + m) * 64 + lane + 32], acc1));
        }
        lp[lane * 5 + t]        = lt0[t] + acc0;
        lp[(lane + 32) * 5 + t] = lt1[t] + acc1;
    }

    // ================= pass B: xq (decoder projection) =================
    {
        unsigned long long u0p[4], u1p[4];
        float u0l, u1l;
        float e0 = ss[S_BD + lane], e1 = ss[S_BD + lane + 32];
        unsigned long long e0s = splat2(e0), e1s = splat2(e1);
#pragma unroll
        for (int j = 0; j < 4; j++) { u0p[j] = e0s; u1p[j] = e1s; }
        u0l = e0; u1l = e1;
#pragma unroll 4
        for (int c = 0; c < 64; c++) {
            float2 wd = __ldg(gWD + c * 32 + lane);
            unsigned long long d0p = splat2(wd.x);
            unsigned long long d1p = splat2(wd.y);
            const float* xr = xp + c * 12;
            unsigned long long xx[4];
#pragma unroll
            for (int j = 0; j < 4; j++)
                xx[j] = *(const unsigned long long*)(xr + 2 * j);
            float x8 = xr[8];
#pragma unroll
            for (int j = 0; j < 4; j++) {
                u0p[j] = ffma2(d0p, xx[j], u0p[j]);
                u1p[j] = ffma2(d1p, xx[j], u1p[j]);
            }
            u0l = fmaf(wd.x, x8, u0l);
            u1l = fmaf(wd.y, x8, u1l);
        }
        // store xq rows (pairs are memory-order consistent)
        unsigned long long* q0 = (unsigned long long*)(xq + lane * 10);
        unsigned long long* q1 = (unsigned long long*)(xq + (lane + 32) * 10);
#pragma unroll
        for (int j = 0; j < 4; j++) { q0[j] = u0p[j]; q1[j] = u1p[j]; }
        xq[lane * 10 + 8]        = u0l;
        xq[(lane + 32) * 10 + 8] = u1l;
    }
    __syncwarp();

    // ================= decoder attention (72 items = h x pos) ============
#pragma unroll
    for (int k = 0; k < 3; k++) {
        int item = lane + 32 * k;
        if (item < 72) {
            int h = item / 9, pos = item - h * 9;
            float sc[4] = {0.f, 0.f, 0.f, 0.f};
#pragma unroll
            for (int d = 0; d < 8; d++) {
                float xv = xq[(h * 8 + d) * 10 + pos];
                const float* lr = lp + (h * 8 + d) * 5;
#pragma unroll
                for (int t = 0; t < 4; t++) sc[t] = fmaf(xv, lr[t], sc[t]);
            }
            float m2 = fmaxf(fmaxf(sc[0], sc[1]), fmaxf(sc[2], sc[3]));
            float es = 0.f;
#pragma unroll
            for (int t = 0; t < 4; t++) { sc[t] = __expf(sc[t] - m2); es += sc[t]; }
            float inv = 1.0f / es;
#pragma unroll
            for (int t = 0; t < 4; t++) sc[t] *= inv;
#pragma unroll
            for (int d = 0; d < 8; d++) {
                const float* lr = lp + (h * 8 + d) * 5;
                float o = 0.f;
#pragma unroll
                for (int t = 0; t < 4; t++) o = fmaf(sc[t], lr[t], o);
                xq[(h * 8 + d) * 10 + pos] = o;   // own (h,pos) slots only
            }
        }
    }
    __syncthreads();

    // cooperative un-patchify store with residual
    for (int i = tid; i < 64 * 3 * 24; i += NT) {
        int col = i % 24;
        int seg = i / 24;
        int p0  = seg % 3;
        int c   = seg / 3;
        int wl  = col / 3, p1 = col % 3;
        int pos = p0 * 3 + p1;
        out[((b * 64 + c) * Hn + hp * 3 + p0) * Wn + wblk * 24 + col] =
            sxq[wl * XQS + c * 10 + pos] + sxp[wl * XPS + c * 12 + pos];
    }
}

extern "C" void kernel_launch(void* const* d_in, const int* in_sizes, int n_in,
                              void* d_out, int out_size) {
    const float* x       = (const float*)d_in[0];
    const float* latent  = (const float*)d_in[1];
    const float* weights = (const float*)d_in[2];
    const float* enc_w   = (const float*)d_in[3];
    const float* enc_b   = (const float*)d_in[4];
    const float* dec_w   = (const float*)d_in[5];
    const float* dec_b   = (const float*)d_in[6];
    float* out = (float*)d_out;

    cudaFuncSetAttribute(nsb_kernel,
                         cudaFuncAttributeMaxDynamicSharedMemorySize, SMEM_B);

    setup_kernel<<<1, 256>>>(latent, weights, enc_w, enc_b, dec_w, dec_b);
    nsb_kernel<<<GRID, NT, SMEM_B>>>(x, out);
}